// round 1
// baseline (speedup 1.0000x reference)
#include <cuda_runtime.h>

// x: [B=65536, C=1, H=28, W=28] fp32
// For each sample b, row h is replaced by its scalar mean iff pos[h] < t[b],
// where pos is the inverse permutation of rows_t (length 28).

#define HDIM 28
#define WDIM 28
#define ROW_F4 7          // 28 floats = 7 float4
#define THREADS 256

__global__ void row_avg_kernel(const float* __restrict__ x,
                               const int* __restrict__ t,
                               const int* __restrict__ rows_t,
                               float* __restrict__ out,
                               int total_rows) {
    __shared__ int s_pos[HDIM];
    if (threadIdx.x < HDIM) {
        // pos[rows_t[i]] = i
        int row = rows_t[threadIdx.x];
        s_pos[row] = threadIdx.x;
    }
    __syncthreads();

    int r = blockIdx.x * blockDim.x + threadIdx.x;
    if (r >= total_rows) return;

    int b = r / HDIM;
    int h = r - b * HDIM;

    const float4* src = reinterpret_cast<const float4*>(x) + (size_t)r * ROW_F4;
    float4 v[ROW_F4];
#pragma unroll
    for (int i = 0; i < ROW_F4; ++i) v[i] = src[i];

    float s = 0.0f;
#pragma unroll
    for (int i = 0; i < ROW_F4; ++i) {
        s += v[i].x + v[i].y + v[i].z + v[i].w;
    }
    float mean = s * (1.0f / (float)WDIM);

    bool replace = (s_pos[h] < t[b]);

    float4* dst = reinterpret_cast<float4*>(out) + (size_t)r * ROW_F4;
    if (replace) {
        float4 m = make_float4(mean, mean, mean, mean);
#pragma unroll
        for (int i = 0; i < ROW_F4; ++i) dst[i] = m;
    } else {
#pragma unroll
        for (int i = 0; i < ROW_F4; ++i) dst[i] = v[i];
    }
}

extern "C" void kernel_launch(void* const* d_in, const int* in_sizes, int n_in,
                              void* d_out, int out_size) {
    const float* x      = (const float*)d_in[0];
    const int*   t      = (const int*)d_in[1];
    const int*   rows_t = (const int*)d_in[2];
    float*       out    = (float*)d_out;

    int total_rows = in_sizes[0] / WDIM;   // B*C*H = 65536*28
    int blocks = (total_rows + THREADS - 1) / THREADS;
    row_avg_kernel<<<blocks, THREADS>>>(x, t, rows_t, out, total_rows);
}

// round 2
// speedup vs baseline: 1.2502x; 1.2502x over previous
#include <cuda_runtime.h>

// x: [B=65536, C=1, H=28, W=28] fp32. Row h of sample b is replaced by its
// mean iff pos[h] < t[b], pos = inverse permutation of rows_t.
//
// Coalesced smem-staged version: 256 rows per block (28 KB tile).

#define HDIM 28
#define WDIM 28
#define ROW_F4 7                 // 28 floats = 7 float4
#define THREADS 256
#define TILE_F4 (THREADS * ROW_F4)   // 1792 float4 = 256 rows

__global__ __launch_bounds__(THREADS)
void row_avg_kernel(const float4* __restrict__ x,
                    const int* __restrict__ t,
                    const int* __restrict__ rows_t,
                    float4* __restrict__ out) {
    __shared__ float4 s_tile[TILE_F4];     // 28 KB
    __shared__ float  s_mean[THREADS];
    __shared__ int    s_rep[THREADS];
    __shared__ int    s_pos[HDIM];

    const int tid = threadIdx.x;
    if (tid < HDIM) {
        s_pos[rows_t[tid]] = tid;          // pos[rows_t[i]] = i
    }

    const long long base_f4 = (long long)blockIdx.x * TILE_F4;

    // ---- Load phase: fully coalesced float4 loads, mirror into smem ----
    float4 v[ROW_F4];
#pragma unroll
    for (int j = 0; j < ROW_F4; ++j) {
        int k = tid + j * THREADS;
        v[j] = x[base_f4 + k];
        s_tile[k] = v[j];
    }
    __syncthreads();

    // ---- Reduce phase: thread tid owns local row tid (conflict-free LDS) ----
    {
        float s = 0.0f;
#pragma unroll
        for (int j = 0; j < ROW_F4; ++j) {
            float4 w = s_tile[tid * ROW_F4 + j];
            s += (w.x + w.y) + (w.z + w.w);
        }
        s_mean[tid] = s * (1.0f / (float)WDIM);

        int gr = blockIdx.x * THREADS + tid;   // global row index
        int b  = gr / HDIM;
        int h  = gr - b * HDIM;
        s_rep[tid] = (s_pos[h] < t[b]) ? 1 : 0;
    }
    __syncthreads();

    // ---- Write phase: coalesced float4 stores from registers/means ----
#pragma unroll
    for (int j = 0; j < ROW_F4; ++j) {
        int k = tid + j * THREADS;
        int row = k / ROW_F4;                  // each float4 lies in one row
        float4 o;
        if (s_rep[row]) {
            float m = s_mean[row];
            o = make_float4(m, m, m, m);
        } else {
            o = v[j];
        }
        out[base_f4 + k] = o;
    }
}

extern "C" void kernel_launch(void* const* d_in, const int* in_sizes, int n_in,
                              void* d_out, int out_size) {
    const float4* x      = (const float4*)d_in[0];
    const int*    t      = (const int*)d_in[1];
    const int*    rows_t = (const int*)d_in[2];
    float4*       out    = (float4*)d_out;

    int total_rows = in_sizes[0] / WDIM;           // 1,835,008
    int blocks = (total_rows + THREADS - 1) / THREADS;   // 7168 exactly
    row_avg_kernel<<<blocks, THREADS>>>(x, t, rows_t, out);
}